// round 16
// baseline (speedup 1.0000x reference)
#include <cuda_runtime.h>
#include <cuda_fp16.h>
#include <mma.h>
#include <math.h>
#include <stdint.h>

using namespace nvcuda;

// Problem constants
#define B_    128
#define D_    2048
#define C_    16522
#define KNN_  6
#define BM    128
#define KC    32             // f32 K-elements per pipeline chunk
#define LDA   40             // KC + 8 pad (halfs)
#define LDE   136            // epilogue f32 row stride (128 + 8)
#define NCHUNK (D_ / KC)     // 64
#define NTILE  130           // ceil(C_/128)
#define NTHR  256

// Per-tile softmax partials
static __device__ float g_pm[B_ * NTILE];
static __device__ float g_ps[B_ * NTILE];
static __device__ float g_tv6[B_ * NTILE * KNN_];
static __device__ int   g_ti6[B_ * NTILE * KNN_];
static __device__ float g_vlab[B_];
static __device__ float g_rowloss[B_];
static __device__ int   g_done = 0;

// Staging (R4 layout): 2 stages x {A, B}, each 128 x LDA fp16 = 40960 B.
// Epilogue reuses dynamic smem as LT[128][LDE] f32 = 69632 B (the max).
struct Smem {
    __half A[2][BM * LDA];
    __half Bm[2][BM * LDA];
};
#define SMEM_DYN (128 * LDE * 4)      // 69632 > sizeof(Smem)=40960

// ---------------------------------------------------------------------------
// Fused kernel: R4's fp16 HMMA GEMM mainloop (256 thr, measured 92.9 us)
//   + fused em->out copy
//   + per-tile partial softmax/top-6 epilogue (2 thr/row, two-pass)
//   + fused EMA update for owned label rows.
// ---------------------------------------------------------------------------
__global__ __launch_bounds__(NTHR, 1) void gemm_fused(const float* __restrict__ X,
                                                      const float* __restrict__ Em,
                                                      const int* __restrict__ label,
                                                      const int* __restrict__ epoch_p,
                                                      float* __restrict__ out1) {
    extern __shared__ char smraw[];
    Smem* sm = (Smem*)smraw;

    const int tid  = threadIdx.x;
    const int wid  = tid >> 5;
    const int lane = tid & 31;
    const int bt   = blockIdx.x;
    const int c0   = bt * BM;
    const int wm   = (wid & 3) * 32;   // warp M origin (classes)
    const int wn   = (wid >> 2) * 64;  // warp N origin (batch)

    wmma::fragment<wmma::accumulator, 16, 16, 16, float> acc[2][4];
    #pragma unroll
    for (int i = 0; i < 2; i++)
        #pragma unroll
        for (int j = 0; j < 4; j++) wmma::fill_fragment(acc[i][j], 0.0f);

    float4 pf[8];   // prefetch: 8 float4 = 32 f32 per thread per chunk

    auto ldchunk = [&](int chunk) {
        const int k0 = chunk * KC;
        #pragma unroll
        for (int t = 0; t < 8; t++) {
            const int g   = tid + t * NTHR;     // 0..2047
            const int mat = g >> 10;            // 0 = A(em), 1 = B(X)
            const int idx = g & 1023;
            const int row = idx >> 3;
            const int q   = idx & 7;
            if (mat == 0) {
                const int c = c0 + row;
                pf[t] = (c < C_) ? __ldcs((const float4*)(Em + (long long)c * D_ + k0 + q * 4))
                                 : make_float4(0.f, 0.f, 0.f, 0.f);
            } else {
                pf[t] = *(const float4*)(X + (long long)row * D_ + k0 + q * 4);
            }
        }
    };

    auto stchunk = [&](int chunk, int st) {
        const int k0 = chunk * KC;
        #pragma unroll
        for (int t = 0; t < 8; t++) {
            const int g   = tid + t * NTHR;
            const int mat = g >> 10;
            const int idx = g & 1023;
            const int row = idx >> 3;
            const int q   = idx & 7;
            float4 f = pf[t];
            __half2 h0 = __float22half2_rn(make_float2(f.x, f.y));
            __half2 h1 = __float22half2_rn(make_float2(f.z, f.w));
            __half* hb = mat ? sm->Bm[st] : sm->A[st];
            const int so = row * LDA + q * 4;
            *(__half2*)(hb + so)     = h0;
            *(__half2*)(hb + so + 2) = h1;
            if (mat == 0 && c0 + row < C_) {
                float* o = out1 + (long long)(c0 + row) * D_ + k0 + q * 4;
                __stcs(o + 0, f.x); __stcs(o + 1, f.y);
                __stcs(o + 2, f.z); __stcs(o + 3, f.w);
            }
        }
    };

    // ---- R4 pipeline: ld(s+1) | mma(s) | st(s+1), 2 syncs per chunk ----
    ldchunk(0);
    stchunk(0, 0);
    __syncthreads();

    for (int s = 0; s < NCHUNK; s++) {
        const int st = s & 1;
        if (s + 1 < NCHUNK) ldchunk(s + 1);

        #pragma unroll
        for (int kk = 0; kk < KC; kk += 16) {
            wmma::fragment<wmma::matrix_a, 16, 16, 16, __half, wmma::row_major> af[2];
            wmma::fragment<wmma::matrix_b, 16, 16, 16, __half, wmma::col_major> bf[4];
            #pragma unroll
            for (int i = 0; i < 2; i++)
                wmma::load_matrix_sync(af[i], sm->A[st] + (wm + i * 16) * LDA + kk, LDA);
            #pragma unroll
            for (int j = 0; j < 4; j++)
                wmma::load_matrix_sync(bf[j], sm->Bm[st] + (wn + j * 16) * LDA + kk, LDA);
            #pragma unroll
            for (int i = 0; i < 2; i++)
                #pragma unroll
                for (int j = 0; j < 4; j++)
                    wmma::mma_sync(acc[i][j], af[i], bf[j], acc[i][j]);
        }
        __syncthreads();
        if (s + 1 < NCHUNK) {
            stchunk(s + 1, st ^ 1);
            __syncthreads();
        }
    }

    // ================= epilogue: tile -> smem batch-major ==================
    __shared__ int   lab[B_];
    __shared__ float red[9];
    __shared__ float tvv[NTHR][KNN_];
    __shared__ int   tii[NTHR][KNN_];

    if (tid < B_) lab[tid] = label[tid];
    __syncthreads();   // staging reads done; reuse smem as LT

    float* LT = (float*)smraw;   // LT[n][c] = D(c, n), stride LDE
    #pragma unroll
    for (int i = 0; i < 2; i++)
        #pragma unroll
        for (int j = 0; j < 4; j++)
            wmma::store_matrix_sync(LT + (wn + j * 16) * LDE + (wm + i * 16),
                                    acc[i][j], LDE, wmma::mem_col_major);
    __syncthreads();

    if (c0 + BM > C_) {   // mask invalid class columns (last tile only)
        for (int idx = tid; idx < BM * B_; idx += NTHR) {
            int c = idx & 127, n = idx >> 7;
            if (c0 + c >= C_) LT[n * LDE + c] = -INFINITY;
        }
        __syncthreads();
    }

    // -------- per-thread partial over 64 classes of one batch row ----------
    {
        const int n   = tid >> 1;
        const int seg = tid & 1;
        const float* src = LT + n * LDE + seg * 64;

        // pass 1: max
        float mt = -INFINITY;
        #pragma unroll
        for (int q = 0; q < 16; q++) {
            float4 f = *(const float4*)(src + q * 4);
            mt = fmaxf(mt, fmaxf(fmaxf(f.x, f.y), fmaxf(f.z, f.w)));
        }
        mt *= 20.0f;   // values scaled by 20 below; -inf stays -inf

        // pass 2: exp-sum + top-6 insert
        float st_ = 0.f;
        float tv[KNN_]; int ti[KNN_];
        #pragma unroll
        for (int j = 0; j < KNN_; j++) { tv[j] = -INFINITY; ti[j] = -1; }

        #pragma unroll
        for (int q = 0; q < 16; q++) {
            float4 f = *(const float4*)(src + q * 4);
            float v0 = f.x * 20.0f, v1 = f.y * 20.0f, v2 = f.z * 20.0f, v3 = f.w * 20.0f;
            if (mt > -INFINITY) {
                __half2 e0 = h2exp(__floats2half2_rn(v0 - mt, v1 - mt));
                __half2 e1 = h2exp(__floats2half2_rn(v2 - mt, v3 - mt));
                float2 a0 = __half22float2(e0), a1 = __half22float2(e1);
                st_ += a0.x + a0.y + a1.x + a1.y;
            }
            float vv[4] = {v0, v1, v2, v3};
            #pragma unroll
            for (int u = 0; u < 4; u++) {
                float x = vv[u];
                if (x > tv[KNN_ - 1]) {
                    int p = KNN_ - 1;
                    while (p > 0 && x > tv[p - 1]) { tv[p] = tv[p - 1]; ti[p] = ti[p - 1]; p--; }
                    tv[p] = x; ti[p] = seg * 64 + q * 4 + u;
                }
            }
        }

        // merge (m, s) across the seg pair (lanes tid, tid^1 in same warp)
        float m_ = mt, s_ = st_;
        {
            float mo = __shfl_xor_sync(0xffffffffu, m_, 1);
            float so = __shfl_xor_sync(0xffffffffu, s_, 1);
            float mm = fmaxf(m_, mo);
            float a  = (s_ > 0.f) ? s_ * __expf(m_ - mm) : 0.f;
            float b2 = (so > 0.f) ? so * __expf(mo - mm) : 0.f;
            m_ = mm; s_ = a + b2;
        }

        #pragma unroll
        for (int j = 0; j < KNN_; j++) { tvv[tid][j] = tv[j]; tii[tid][j] = ti[j]; }
        __syncwarp();

        if (seg == 0) {
            // merge 2 descending lists -> tile top-6
            int p[2] = {0, 0};
            float otv[KNN_]; int oti[KNN_];
            #pragma unroll
            for (int r = 0; r < KNN_; r++) {
                float bv = -INFINITY; int bs = -1;
                #pragma unroll
                for (int q = 0; q < 2; q++) {
                    if (p[q] < KNN_) {
                        float cv_ = tvv[tid + q][p[q]];
                        if (cv_ > bv) { bv = cv_; bs = q; }
                    }
                }
                otv[r] = bv;
                oti[r] = (bs >= 0) ? c0 + tii[tid + bs][p[bs]] : -1;
                if (bs >= 0) p[bs]++;
            }
            const int o = n * NTILE + bt;
            g_pm[o] = m_;
            g_ps[o] = s_;
            #pragma unroll
            for (int j = 0; j < KNN_; j++) { g_tv6[o * KNN_ + j] = otv[j]; g_ti6[o * KNN_ + j] = oti[j]; }

            const int y = lab[n];
            if (y >= c0 && y < c0 + BM)
                g_vlab[n] = LT[n * LDE + (y - c0)] * 20.0f;
        }
    }
    __syncthreads();

    // ---------------- fused EMA update for owned label rows ----------------
    bool any = false;
    for (int b = 0; b < B_; b++)
        if (lab[b] >= c0 && lab[b] < c0 + BM) { any = true; break; }
    if (!any) return;

    const float alpha = 0.01f * (float)epoch_p[0];

    for (int b = 0; b < B_; b++) {
        const int y = lab[b];
        if (y < c0 || y >= c0 + BM) continue;
        bool head = true;
        for (int j = 0; j < b; j++)
            if (lab[j] == y) { head = false; break; }
        if (!head) continue;

        float r[8];
        #pragma unroll
        for (int k = 0; k < 8; k++) r[k] = Em[(long long)y * D_ + k * NTHR + tid];

        for (int i = b; i < B_; i++) {
            if (lab[i] != y) continue;
            float sq = 0.f;
            #pragma unroll
            for (int k = 0; k < 8; k++) {
                r[k] = alpha * r[k] + (1.f - alpha) * X[i * D_ + k * NTHR + tid];
                sq = fmaf(r[k], r[k], sq);
            }
            #pragma unroll
            for (int o = 16; o > 0; o >>= 1) sq += __shfl_xor_sync(0xffffffffu, sq, o);
            if (lane == 0) red[wid] = sq;
            __syncthreads();
            if (tid == 0) {
                float tot = 0.f;
                #pragma unroll
                for (int w = 0; w < 8; w++) tot += red[w];
                red[8] = tot;
            }
            __syncthreads();
            float inv = rsqrtf(red[8]);
            __syncthreads();
            #pragma unroll
            for (int k = 0; k < 8; k++) r[k] *= inv;
        }

        #pragma unroll
        for (int k = 0; k < 8; k++) out1[(long long)y * D_ + k * NTHR + tid] = r[k];
    }
}

// ---------------------------------------------------------------------------
// Combine (R11-verbatim): one block (128 thr) per batch row.
// ---------------------------------------------------------------------------
__global__ __launch_bounds__(128) void combine_kernel(const int* __restrict__ label,
                                                      float* __restrict__ loss_out) {
    const int tid  = threadIdx.x;
    const int lane = tid & 31;
    const int wrp  = tid >> 5;
    const int b    = blockIdx.x;

    float m = -INFINITY, s = 0.f;
    float tv[KNN_]; int ti[KNN_];
    #pragma unroll
    for (int j = 0; j < KNN_; j++) { tv[j] = -INFINITY; ti[j] = -1; }

    for (int t = tid; t < NTILE; t += 128) {
        const int o = b * NTILE + t;
        float mo = g_pm[o], so = g_ps[o];
        float mm = fmaxf(m, mo);
        float a  = (s  > 0.f) ? s  * __expf(m  - mm) : 0.f;
        float c2 = (so > 0.f) ? so * __expf(mo - mm) : 0.f;
        m = mm; s = a + c2;
        #pragma unroll
        for (int j = 0; j < KNN_; j++) {
            float x = g_tv6[o * KNN_ + j];
            if (x > tv[KNN_ - 1]) {
                int xi = g_ti6[o * KNN_ + j];
                int p = KNN_ - 1;
                while (p > 0 && x > tv[p - 1]) { tv[p] = tv[p - 1]; ti[p] = ti[p - 1]; p--; }
                tv[p] = x; ti[p] = xi;
            } else break;
        }
    }

    #pragma unroll
    for (int o = 16; o > 0; o >>= 1) {
        float mo = __shfl_xor_sync(0xffffffffu, m, o);
        float so = __shfl_xor_sync(0xffffffffu, s, o);
        float mm = fmaxf(m, mo);
        float a  = (s  > 0.f) ? s  * __expf(m  - mm) : 0.f;
        float c2 = (so > 0.f) ? so * __expf(mo - mm) : 0.f;
        m = mm; s = a + c2;
    }

    float wtv[KNN_]; int wti[KNN_];
    {
        int p = 0;
        #pragma unroll
        for (int r = 0; r < KNN_; r++) {
            float cand = (p < KNN_) ? tv[p] : -INFINITY;
            int   cidx = (p < KNN_) ? ti[p] : -1;
            float bv = cand; int bl = lane;
            #pragma unroll
            for (int o = 16; o > 0; o >>= 1) {
                float ov = __shfl_xor_sync(0xffffffffu, bv, o);
                int   ol = __shfl_xor_sync(0xffffffffu, bl, o);
                if (ov > bv || (ov == bv && ol < bl)) { bv = ov; bl = ol; }
            }
            int widx = __shfl_sync(0xffffffffu, cidx, bl);
            if (lane == bl) p++;
            wtv[r] = bv; wti[r] = widx;
        }
    }

    __shared__ float smm[4], sms[4];
    __shared__ float swv[4][KNN_];
    __shared__ int   swi[4][KNN_];
    if (lane == 0) { smm[wrp] = m; sms[wrp] = s; }
    if (lane < KNN_) { swv[wrp][lane] = wtv[lane]; swi[wrp][lane] = wti[lane]; }
    __syncthreads();

    if (wrp == 0) {
        float fm = smm[0], fs = sms[0];
        #pragma unroll
        for (int w = 1; w < 4; w++) {
            float mo = smm[w], so = sms[w];
            float mm2 = fmaxf(fm, mo);
            float a  = (fs > 0.f) ? fs * __expf(fm - mm2) : 0.f;
            float c2 = (so > 0.f) ? so * __expf(mo - mm2) : 0.f;
            fm = mm2; fs = a + c2;
        }
        const float LSE = fm + logf(fs);

        float cand = (lane < 24) ? swv[lane / KNN_][lane % KNN_] : -INFINITY;
        int   cidx = (lane < 24) ? swi[lane / KNN_][lane % KNN_] : -1;

        const int y = label[b];
        float sum6 = 0.f;
        int   in = 0;
        #pragma unroll
        for (int r = 0; r < KNN_; r++) {
            float bv = cand; int bl = lane;
            #pragma unroll
            for (int o = 16; o > 0; o >>= 1) {
                float ov = __shfl_xor_sync(0xffffffffu, bv, o);
                int   ol = __shfl_xor_sync(0xffffffffu, bl, o);
                if (ov > bv || (ov == bv && ol < bl)) { bv = ov; bl = ol; }
            }
            int widx = __shfl_sync(0xffffffffu, cidx, bl);
            if (lane == bl) cand = -INFINITY;
            sum6 += (LSE - bv);
            if (widx == y) in = 1;
        }

        if (lane == 0) {
            float ll = LSE - g_vlab[b];
            g_rowloss[b] = 2.f * sum6 + (3.f - 2.f * (float)in) * ll;
        }
    }

    __shared__ int is_last;
    __syncthreads();
    if (tid == 0) {
        __threadfence();
        is_last = (atomicAdd(&g_done, 1) == B_ - 1);
    }
    __syncthreads();
    if (is_last && tid < 32) {
        float accv = 0.f;
        #pragma unroll
        for (int k = 0; k < 4; k++) accv += g_rowloss[tid + k * 32];
        #pragma unroll
        for (int o = 16; o > 0; o >>= 1) accv += __shfl_xor_sync(0xffffffffu, accv, o);
        if (tid == 0) {
            loss_out[0] = accv / (float)B_;
            g_done = 0;
        }
    }
}

// ---------------------------------------------------------------------------
// Launch
// ---------------------------------------------------------------------------
extern "C" void kernel_launch(void* const* d_in, const int* in_sizes, int n_in,
                              void* d_out, int out_size) {
    const float* X     = (const float*)d_in[0];  // [128, 2048] f32
    const int*   label = (const int*)  d_in[1];  // [128] i32
    const float* Em    = (const float*)d_in[2];  // [16522, 2048] f32
    const int*   epoch = (const int*)  d_in[3];  // scalar

    float* out = (float*)d_out;                  // [0]=loss, [1..]=em_new

    cudaFuncSetAttribute(gemm_fused, cudaFuncAttributeMaxDynamicSharedMemorySize, SMEM_DYN);

    gemm_fused    <<<NTILE, NTHR, SMEM_DYN>>>(X, Em, label, epoch, out + 1);
    combine_kernel<<<B_, 128>>>(label, out);
}